// round 6
// baseline (speedup 1.0000x reference)
#include <cuda_runtime.h>
#include <cuda_bf16.h>
#include <cuda_fp16.h>
#include <math.h>

#define Hh 128
#define Rr 50
#define Ll 4
#define Nn 10000
#define Mm 64
#define NP 10112           // 79 * 128
#define EMAX 2000000
#define BINS 2048
#define SCALE ((float)BINS / 5.0f)
#define STEP (5.0f / (float)BINS)
#define TBB 64             // bins per table-build block

typedef unsigned long long u64;

__device__ __forceinline__ void fma2(u64 &d, u64 a, u64 b) {
    asm("fma.rn.f32x2 %0, %1, %2, %0;" : "+l"(d) : "l"(a), "l"(b));
}
__device__ __forceinline__ u64 pack2(float lo, float hi) {
    u64 r; asm("mov.b64 %0, {%1, %2};" : "=l"(r) : "f"(lo), "f"(hi)); return r;
}
__device__ __forceinline__ void unpack2(u64 v, float &lo, float &hi) {
    asm("mov.b64 {%0, %1}, %2;" : "=f"(lo), "=f"(hi) : "l"(v));
}

__device__ __forceinline__ float gru_upd(float xo, float rv, float zv, float nv,
                                         float bhr, float bhz, float bhn) {
    float r = __fdividef(1.f, 1.f + __expf(-(rv + bhr)));
    float z = __fdividef(1.f, 1.f + __expf(-(zv + bhz)));
    float t = nv + r * bhn;
    float e = __expf(2.f * t);
    float th = 1.f - __fdividef(2.f, e + 1.f);
    return xo + (1.f - z) * th;
}

__device__ __forceinline__ float silu_f(float p) {
    float e = __expf(-p);
    float r;
    asm("rcp.approx.f32 %0, %1;" : "=f"(r) : "f"(1.f + e));
    return p * r;
}

// ---------------- scratch ----------------
__device__ float   g_x[NP * Hh];
__device__ float   g_y[NP * Hh];
__device__ float   g_S[NP * Hh];
__device__ float   g_gi[NP * 3 * Hh];
__device__ float   g_d[EMAX];
__device__ int     g_rp[Nn + 1];
__device__ float   g_sums[Mm * Hh];
__device__ float   g_cnt[Mm];
__device__ __half2 g_tabh[Ll * BINS * Hh];   // (val, slope) per channel
__device__ float   g_Wc[Ll * Hh * 3 * Hh];
__device__ float   g_bc2[Ll * 3 * Hh];
__device__ int     g_ctr;

// ---------------- prep0: init x (+pads), zero sums/cnt, build row_ptr ----------------
__global__ void prep0(const int* __restrict__ an, const float* __restrict__ emb,
                      const int* __restrict__ rowp, int E,
                      float* __restrict__ x, float* __restrict__ sums,
                      float* __restrict__ cnt, int* __restrict__ rp) {
    int i = blockIdx.x * blockDim.x + threadIdx.x;
    if (i < NP * Hh) {
        int n = i >> 7, ch = i & 127;
        if (n < Nn) {
            int a = an[n];
            a = a < 0 ? 0 : (a > 99 ? 99 : a);
            x[i] = emb[a * Hh + ch];
        } else {
            x[i] = 0.f;
        }
        return;
    }
    int i2 = i - NP * Hh;
    if (i2 < Mm * Hh) { sums[i2] = 0.f; return; }
    i2 -= Mm * Hh;
    if (i2 < Mm) { cnt[i2] = 0.f; return; }
    int e = i2 - Mm;
    if (e > E) return;
    if (e == 0) {
        int b = rowp[0];
        for (int r = 0; r <= b; r++) rp[r] = 0;
    } else if (e == E) {
        int a = rowp[E - 1];
        for (int r = a + 1; r <= Nn; r++) rp[r] = E;
    } else {
        int a = rowp[e - 1], b = rowp[e];
        for (int r = a + 1; r <= b; r++) rp[r] = e;
    }
}

// ---------------- prep1: edge distances + fp16 rbf table (tiled) + bc2 ----------------
__global__ void prep1(const float* __restrict__ pos, const int* __restrict__ rowp,
                      const int* __restrict__ colp, int E, int ndb,
                      const float* __restrict__ W1, const float* __restrict__ W_ih,
                      const float* __restrict__ b2,
                      float* __restrict__ dv, __half2* __restrict__ tab,
                      float* __restrict__ bc2) {
    __shared__ float basis[(TBB + 1) * Rr];
    int tid = threadIdx.x;
    int blk = blockIdx.x;
    if (blk < ndb) {
        int e = blk * 128 + tid;
        if (e < E) {
            int r = rowp[e], c = colp[e];
            float dx = pos[r * 3 + 0] - pos[c * 3 + 0];
            float dy = pos[r * 3 + 1] - pos[c * 3 + 1];
            float dz = pos[r * 3 + 2] - pos[c * 3 + 2];
            dv[e] = sqrtf(dx * dx + dy * dy + dz * dz);
        }
        return;
    }
    int t = blk - ndb;
    const int TBLKS = BINS / TBB;                 // 32 per layer
    if (t < TBLKS * Ll) {
        int l = t / TBLKS, bt = t - l * TBLKS;
        int bin0 = bt * TBB;
        // cooperative basis: rbf at TBB+1 bin boundaries x Rr centers
        for (int i = tid; i < (TBB + 1) * Rr; i += 128) {
            int g = i / Rr, k = i - g * Rr;
            float c = (float)k * (5.0f / 49.0f);
            float d0 = (float)(bin0 + g) * STEP - c;
            basis[i] = expf(-50.0f * d0 * d0);
        }
        __syncthreads();
        // per-thread channel: w column in registers
        const float* W1b = W1 + l * (Hh + Rr) * Hh + Hh * Hh;
        float w[Rr];
#pragma unroll
        for (int k = 0; k < Rr; k++) w[k] = W1b[k * Hh + tid];
        float vprev = 0.f;
#pragma unroll
        for (int k = 0; k < Rr; k++) vprev += basis[k] * w[k];
        for (int g = 1; g <= TBB; g++) {
            float v = 0.f;
            const float* bs = &basis[g * Rr];
#pragma unroll
            for (int k = 0; k < Rr; k++) v += bs[k] * w[k];
            tab[((l * BINS + bin0 + g - 1) << 7) + tid] =
                __floats2half2_rn(vprev, v - vprev);
            vprev = v;
        }
        return;
    }
    int t2 = t - TBLKS * Ll;           // [0, 12): bc2 = b2 @ W_ih
    int l = t2 / 3, chunk = t2 - l * 3;
    int n = chunk * 128 + tid;
    const float* W = W_ih + l * Hh * 3 * Hh;
    const float* b = b2 + l * Hh;
    float s = 0.f;
#pragma unroll 8
    for (int k = 0; k < Hh; k++) s += b[k] * W[k * 3 * Hh + n];
    bc2[l * 3 * Hh + n] = s;
}

// ---------------- f32x2 GEMM, tile 128x128, optional fused GRU prologue ----------------
__global__ void __launch_bounds__(256, 2)
gemm_f2b(const float* __restrict__ A, const float* __restrict__ B,
         const float* __restrict__ bias, const int* __restrict__ rp,
         const float* __restrict__ bias2,
         const float* __restrict__ gi, const float* __restrict__ bhh,
         float* __restrict__ xout,
         float* __restrict__ C, int Nr,
         int aSz, int bSz, int cSz) {
    __shared__ float As[16][132];
    __shared__ float Bs[16][128];
    int tid = threadIdx.x;
    int tx = tid & 15, ty = tid >> 4;
    int m0 = blockIdx.y * 128, n0 = blockIdx.x * 128;
    const float* Ab = A + (size_t)blockIdx.z * aSz;
    const float* Bb = B + (size_t)blockIdx.z * bSz;
    float* Cb = C + (size_t)blockIdx.z * cSz;
    u64 acc[4][8] = {};
    for (int kk = 0; kk < 128; kk += 16) {
#pragma unroll
        for (int it = 0; it < 2; it++) {
            int r = (tid >> 2) + it * 64;
            int c4 = (tid & 3) << 2;
            int m = m0 + r;
            float4 v = *(const float4*)(Ab + (size_t)m * 128 + kk + c4);
            if (gi) {
                const float* gm = gi + (size_t)m * 384 + kk + c4;
                float4 rv = __ldg((const float4*)(gm));
                float4 zv = __ldg((const float4*)(gm + 128));
                float4 nv = __ldg((const float4*)(gm + 256));
                float4 br = __ldg((const float4*)(bhh + kk + c4));
                float4 bz = __ldg((const float4*)(bhh + 128 + kk + c4));
                float4 bn = __ldg((const float4*)(bhh + 256 + kk + c4));
                v.x = gru_upd(v.x, rv.x, zv.x, nv.x, br.x, bz.x, bn.x);
                v.y = gru_upd(v.y, rv.y, zv.y, nv.y, br.y, bz.y, bn.y);
                v.z = gru_upd(v.z, rv.z, zv.z, nv.z, br.z, bz.z, bn.z);
                v.w = gru_upd(v.w, rv.w, zv.w, nv.w, br.w, bz.w, bn.w);
                *(float4*)(xout + (size_t)m * 128 + kk + c4) = v;
            }
            As[c4 + 0][r] = v.x; As[c4 + 1][r] = v.y;
            As[c4 + 2][r] = v.z; As[c4 + 3][r] = v.w;
        }
        {
            int r = tid >> 4, c8 = (tid & 15) << 3;
            *(float4*)&Bs[r][c8]     = *(const float4*)(Bb + (size_t)(kk + r) * Nr + n0 + c8);
            *(float4*)&Bs[r][c8 + 4] = *(const float4*)(Bb + (size_t)(kk + r) * Nr + n0 + c8 + 4);
        }
        __syncthreads();
#pragma unroll
        for (int k = 0; k < 16; k++) {
            longlong2 la = *(const longlong2*)&As[k][ty * 8];
            longlong2 lb = *(const longlong2*)&As[k][ty * 8 + 4];
            float4 b0 = *(const float4*)&Bs[k][tx * 8];
            float4 b1 = *(const float4*)&Bs[k][tx * 8 + 4];
            u64 ap[4] = { (u64)la.x, (u64)la.y, (u64)lb.x, (u64)lb.y };
            u64 bp[8] = { pack2(b0.x, b0.x), pack2(b0.y, b0.y),
                          pack2(b0.z, b0.z), pack2(b0.w, b0.w),
                          pack2(b1.x, b1.x), pack2(b1.y, b1.y),
                          pack2(b1.z, b1.z), pack2(b1.w, b1.w) };
#pragma unroll
            for (int i = 0; i < 4; i++)
#pragma unroll
                for (int j = 0; j < 8; j++) fma2(acc[i][j], ap[i], bp[j]);
        }
        __syncthreads();
    }
    float4 bb0 = make_float4(0.f, 0.f, 0.f, 0.f), bb1 = bb0;
    float4 c20 = bb0, c21 = bb0;
    if (bias)  { bb0 = *(const float4*)(bias + n0 + tx * 8);
                 bb1 = *(const float4*)(bias + n0 + tx * 8 + 4); }
    if (bias2) { c20 = *(const float4*)(bias2 + n0 + tx * 8);
                 c21 = *(const float4*)(bias2 + n0 + tx * 8 + 4); }
#pragma unroll
    for (int i = 0; i < 4; i++) {
        int mA = m0 + ty * 8 + 2 * i;
        float dA = 0.f, dB = 0.f;
        if (rp) {
            if (mA < Nn)     dA = (float)(rp[mA + 1] - rp[mA]);
            if (mA + 1 < Nn) dB = (float)(rp[mA + 2] - rp[mA + 1]);
        }
        float lo[8], hi[8];
#pragma unroll
        for (int j = 0; j < 8; j++) unpack2(acc[i][j], lo[j], hi[j]);
        float4 rA0 = make_float4(lo[0] + bb0.x + dA * c20.x, lo[1] + bb0.y + dA * c20.y,
                                 lo[2] + bb0.z + dA * c20.z, lo[3] + bb0.w + dA * c20.w);
        float4 rA1 = make_float4(lo[4] + bb1.x + dA * c21.x, lo[5] + bb1.y + dA * c21.y,
                                 lo[6] + bb1.z + dA * c21.z, lo[7] + bb1.w + dA * c21.w);
        float4 rB0 = make_float4(hi[0] + bb0.x + dB * c20.x, hi[1] + bb0.y + dB * c20.y,
                                 hi[2] + bb0.z + dB * c20.z, hi[3] + bb0.w + dB * c20.w);
        float4 rB1 = make_float4(hi[4] + bb1.x + dB * c21.x, hi[5] + bb1.y + dB * c21.y,
                                 hi[6] + bb1.z + dB * c21.z, hi[7] + bb1.w + dB * c21.w);
        *(float4*)(Cb + (size_t)mA * Nr + n0 + tx * 8)           = rA0;
        *(float4*)(Cb + (size_t)mA * Nr + n0 + tx * 8 + 4)       = rA1;
        *(float4*)(Cb + (size_t)(mA + 1) * Nr + n0 + tx * 8)     = rB0;
        *(float4*)(Cb + (size_t)(mA + 1) * Nr + n0 + tx * 8 + 4) = rB1;
    }
}

// ---------------- warp-per-node CSR edge kernel, fp16 table ----------------
__global__ void __launch_bounds__(128)
edge_csr(const int* __restrict__ rp, const int* __restrict__ colp,
         const float* __restrict__ dvec, const float* __restrict__ y,
         const __half2* __restrict__ tab, float* __restrict__ S) {
    int lane = threadIdx.x & 31;
    int n = blockIdx.x * 4 + (threadIdx.x >> 5);
    if (n >= Nn) return;
    int e0 = rp[n];
    int deg = rp[n + 1] - e0;
    float a0 = 0.f, a1 = 0.f, a2 = 0.f, a3 = 0.f;
    for (int base = 0; base < deg; base += 32) {
        int cnt = min(32, deg - base);
        float u_r = 0.f; int cc_r = 0;
        if (lane < cnt) {
            u_r = __ldg(dvec + e0 + base + lane) * SCALE;
            cc_r = __ldg(colp + e0 + base + lane);
        }
        for (int j = 0; j < cnt; j++) {
            float u = __shfl_sync(~0u, u_r, j);
            int cc = __shfl_sync(~0u, cc_r, j);
            int b = (int)u;
            float f = u - (float)b;
            uint4 tv = __ldg((const uint4*)(tab + (b << 7) + lane * 4));
            float4 yv = __ldg((const float4*)(y + ((size_t)cc << 7)) + lane);
            float2 t0 = __half22float2(*(__half2*)&tv.x);
            float2 t1 = __half22float2(*(__half2*)&tv.y);
            float2 t2 = __half22float2(*(__half2*)&tv.z);
            float2 t3 = __half22float2(*(__half2*)&tv.w);
            float p0 = yv.x + fmaf(f, t0.y, t0.x);
            float p1 = yv.y + fmaf(f, t1.y, t1.x);
            float p2 = yv.z + fmaf(f, t2.y, t2.x);
            float p3 = yv.w + fmaf(f, t3.y, t3.x);
            a0 += silu_f(p0);
            a1 += silu_f(p1);
            a2 += silu_f(p2);
            a3 += silu_f(p3);
        }
    }
    *(float4*)(S + ((size_t)n << 7) + lane * 4) = make_float4(a0, a1, a2, a3);
}

// ---------------- fused GRU(l=3) + LayerNorm + pooling (+final via last block) ----------------
__global__ void __launch_bounds__(256)
ln_pool_all(const float* __restrict__ x, const float* __restrict__ gi,
            const float* __restrict__ bhh, const int* __restrict__ batch,
            const float* __restrict__ lg, const float* __restrict__ lb,
            float* __restrict__ out, float* __restrict__ sums,
            float* __restrict__ cnt, float* __restrict__ out2) {
    __shared__ int s_last;
    int warp = (blockIdx.x * blockDim.x + threadIdx.x) >> 5;
    int lane = threadIdx.x & 31;
    if (warp < Nn) {
        int ch = lane * 4;
        float4 v = __ldg((const float4*)(x + (size_t)warp * Hh + ch));
        const float* gm = gi + (size_t)warp * 384 + ch;
        float4 rv = __ldg((const float4*)(gm));
        float4 zv = __ldg((const float4*)(gm + 128));
        float4 nv = __ldg((const float4*)(gm + 256));
        float4 br = __ldg((const float4*)(bhh + ch));
        float4 bz = __ldg((const float4*)(bhh + 128 + ch));
        float4 bn = __ldg((const float4*)(bhh + 256 + ch));
        v.x = gru_upd(v.x, rv.x, zv.x, nv.x, br.x, bz.x, bn.x);
        v.y = gru_upd(v.y, rv.y, zv.y, nv.y, br.y, bz.y, bn.y);
        v.z = gru_upd(v.z, rv.z, zv.z, nv.z, br.z, bz.z, bn.z);
        v.w = gru_upd(v.w, rv.w, zv.w, nv.w, br.w, bz.w, bn.w);
        float s = v.x + v.y + v.z + v.w;
#pragma unroll
        for (int o = 16; o; o >>= 1) s += __shfl_xor_sync(~0u, s, o);
        float mu = s * (1.0f / 128.0f);
        float dx = v.x - mu, dy = v.y - mu, dz = v.z - mu, dw = v.w - mu;
        float vs = dx * dx + dy * dy + dz * dz + dw * dw;
#pragma unroll
        for (int o = 16; o; o >>= 1) vs += __shfl_xor_sync(~0u, vs, o);
        float inv = rsqrtf(vs * (1.0f / 128.0f) + 1e-5f);
        float o0 = dx * inv * lg[ch + 0] + lb[ch + 0];
        float o1 = dy * inv * lg[ch + 1] + lb[ch + 1];
        float o2 = dz * inv * lg[ch + 2] + lb[ch + 2];
        float o3 = dw * inv * lg[ch + 3] + lb[ch + 3];
        *(float4*)(out + (size_t)warp * Hh + ch) = make_float4(o0, o1, o2, o3);
        int bm = batch[warp];
        atomicAdd(&sums[bm * Hh + ch + 0], o0);
        atomicAdd(&sums[bm * Hh + ch + 1], o1);
        atomicAdd(&sums[bm * Hh + ch + 2], o2);
        atomicAdd(&sums[bm * Hh + ch + 3], o3);
        if (lane == 0) atomicAdd(&cnt[bm], 1.0f);
    }
    __syncthreads();
    if (threadIdx.x == 0) {
        __threadfence();
        int t = atomicAdd(&g_ctr, 1);
        s_last = (t == gridDim.x - 1) ? 1 : 0;
    }
    __syncthreads();
    if (s_last) {
        for (int i = threadIdx.x; i < Mm * Hh; i += blockDim.x) {
            float c = cnt[i >> 7];
            out2[i] = sums[i] / (c < 1.f ? 1.f : c);
        }
        if (threadIdx.x == 0) g_ctr = 0;
    }
}

// ---------------- host launcher ----------------
extern "C" void kernel_launch(void* const* d_in, const int* in_sizes, int n_in,
                              void* d_out, int out_size) {
    const int*   an    = (const int*)d_in[0];
    const float* pos   = (const float*)d_in[1];
    const int*   batch = (const int*)d_in[2];
    const int*   eidx  = (const int*)d_in[3];
    const float* emb   = (const float*)d_in[4];
    const float* W1    = (const float*)d_in[5];
    const float* b1    = (const float*)d_in[6];
    const float* W2    = (const float*)d_in[7];
    const float* b2    = (const float*)d_in[8];
    const float* W_ih  = (const float*)d_in[9];
    const float* b_ih  = (const float*)d_in[10];
    const float* b_hh  = (const float*)d_in[11];
    const float* ln_g  = (const float*)d_in[12];
    const float* ln_b  = (const float*)d_in[13];
    int E = in_sizes[3] / 2;
    if (E > EMAX) E = EMAX;
    const int* rowp = eidx;
    const int* colp = eidx + E;
    float* out = (float*)d_out;

    float *xp, *yp, *Sp, *gp, *dvp, *sp, *cp, *wcp, *bcp;
    __half2* tp;
    int* rpp;
    cudaGetSymbolAddress((void**)&xp,  g_x);
    cudaGetSymbolAddress((void**)&yp,  g_y);
    cudaGetSymbolAddress((void**)&Sp,  g_S);
    cudaGetSymbolAddress((void**)&gp,  g_gi);
    cudaGetSymbolAddress((void**)&dvp, g_d);
    cudaGetSymbolAddress((void**)&rpp, g_rp);
    cudaGetSymbolAddress((void**)&sp,  g_sums);
    cudaGetSymbolAddress((void**)&cp,  g_cnt);
    cudaGetSymbolAddress((void**)&tp,  g_tabh);
    cudaGetSymbolAddress((void**)&wcp, g_Wc);
    cudaGetSymbolAddress((void**)&bcp, g_bc2);

    // 1: init x/pads + zero sums/cnt + row_ptr
    int p0n = NP * Hh + Mm * Hh + Mm + E + 1;
    prep0<<<(p0n + 255) / 256, 256>>>(an, emb, rowp, E, xp, sp, cp, rpp);
    // 2: distances + fp16 rbf table (tiled) + bc2
    int ndb = (E + 127) / 128;
    prep1<<<ndb + (BINS / TBB) * Ll + 12, 128>>>(pos, rowp, colp, E, ndb,
                                                 W1, W_ih, b2, dvp, tp, bcp);
    const int Mt = NP / 128;
    for (int l = 0; l < Ll; l++) {
        const float* W1a = W1 + l * (Hh + Rr) * Hh;
        // y = x' @ W1a + b1   (x' = x + gru(gi_{l-1}) for l>0, stored back to x)
        gemm_f2b<<<dim3(1, Mt), 256>>>(xp, W1a, b1 + l * Hh, nullptr, nullptr,
                                       (l > 0) ? gp : nullptr,
                                       b_hh + (l - 1) * 3 * Hh, xp,
                                       yp, Hh, 0, 0, 0);
        // edge aggregation (warp-per-node CSR, fp16 table)
        edge_csr<<<(Nn + 3) / 4, 128>>>(rpp, colp, dvp, yp, tp + l * BINS * Hh, Sp);
        if (l == 0) {
            // Wc[l] = W2[l] @ W_ih[l], batched over layers
            gemm_f2b<<<dim3(3, 1, Ll), 256>>>(W2, W_ih, nullptr, nullptr, nullptr,
                                              nullptr, nullptr, nullptr,
                                              wcp, 3 * Hh,
                                              Hh * Hh, Hh * 3 * Hh, Hh * 3 * Hh);
        }
        // gi = S @ Wc + b_ih + deg (x) bc2
        gemm_f2b<<<dim3(3, Mt), 256>>>(Sp, wcp + l * Hh * 3 * Hh, b_ih + l * 3 * Hh,
                                       rpp, bcp + l * 3 * Hh,
                                       nullptr, nullptr, nullptr,
                                       gp, 3 * Hh, 0, 0, 0);
    }

    float* out_x = out;
    float* out_rep = out + Nn * Hh;
    if (out_size == Mm * Hh) { out_x = yp; out_rep = out; }
    // fused GRU(l=3) + LayerNorm + pool + finalize
    ln_pool_all<<<(Nn + 7) / 8, 256>>>(xp, gp, b_hh + 3 * 3 * Hh, batch,
                                       ln_g, ln_b, out_x, sp, cp, out_rep);
}